// round 6
// baseline (speedup 1.0000x reference)
#include <cuda_runtime.h>
#include <cuda_fp16.h>

#define H 128
#define NMAX 100000
#define EMAX 1600000

typedef unsigned long long ull;

// ---------------- device scratch (no allocs allowed) ----------------
__device__ ull   g_degsum[NMAX];     // [deg:16][sumw_fixed(2^-32):48]
__device__ int   g_off[NMAX + 1];
__device__ int   g_cur[NMAX];
__device__ int   g_bsum[128];
__device__ int   g_csr[EMAX];
__device__ __align__(16) __half2 g_xh[(size_t)NMAX * (H / 2)];  // fp16 copy of x

__device__ __forceinline__ unsigned f2tf(float f) {
    unsigned r; asm("cvt.rna.tf32.f32 %0, %1;" : "=r"(r) : "f"(f)); return r;
}

// ---------------- x -> fp16 ----------------
__global__ void k_tohalf(const float* __restrict__ x, int n_f4) {
    int i = blockIdx.x * blockDim.x + threadIdx.x;
    if (i >= n_f4) return;
    float4 v = __ldg((const float4*)x + i);
    uint2 o;
    __half2 h0 = __floats2half2_rn(v.x, v.y);
    __half2 h1 = __floats2half2_rn(v.z, v.w);
    o.x = *(unsigned*)&h0;
    o.y = *(unsigned*)&h1;
    ((uint2*)g_xh)[i] = o;
}

// ---------------- CSR build ----------------
__global__ void k_zero(int n) {
    int i = blockIdx.x * blockDim.x + threadIdx.x;
    if (i < n) g_degsum[i] = 0ull;
}

__global__ void k_hist(const int* __restrict__ ei, const float* __restrict__ ew, int E) {
    int e = blockIdx.x * blockDim.x + threadIdx.x;
    if (e >= E) return;
    int d = __ldg(ei + (size_t)E + e);
    float w = __ldg(ew + e);
    ull v = (1ull << 48) + (ull)(w * 4294967296.0f);
    atomicAdd(&g_degsum[d], v);
}

__global__ __launch_bounds__(1024) void k_scan1(int n) {
    __shared__ int sh[1024];
    int tid = threadIdx.x;
    int i = blockIdx.x * 1024 + tid;
    int v = (i < n) ? (int)(g_degsum[i] >> 48) : 0;
    sh[tid] = v;
    __syncthreads();
#pragma unroll
    for (int ofs = 1; ofs < 1024; ofs <<= 1) {
        int t = (tid >= ofs) ? sh[tid - ofs] : 0;
        __syncthreads();
        sh[tid] += t;
        __syncthreads();
    }
    if (i <= n) g_off[i] = sh[tid] - v;
    if (tid == 1023) g_bsum[blockIdx.x] = sh[1023];
}

__global__ __launch_bounds__(1024) void k_scan3(int n, int E) {
    __shared__ int sh[128];
    __shared__ int s_base;
    int tid = threadIdx.x;
    int b = blockIdx.x;
    if (tid < 128) sh[tid] = (tid < b) ? g_bsum[tid] : 0;
    __syncthreads();
    if (tid < 64) sh[tid] += sh[tid + 64];
    __syncthreads();
    if (tid < 32) {
        int v = sh[tid] + sh[tid + 32];
#pragma unroll
        for (int o = 16; o > 0; o >>= 1) v += __shfl_down_sync(0xffffffffu, v, o);
        if (tid == 0) s_base = v;
    }
    __syncthreads();
    int base = s_base;
    int i = b * 1024 + tid;
    if (i < n) {
        int o = g_off[i] + base;
        g_off[i] = o;
        g_cur[i] = o;
    }
    if (i == 0) g_off[n] = E;
}

__global__ void k_fill(const int* __restrict__ ei, int E) {
    int e = blockIdx.x * blockDim.x + threadIdx.x;
    if (e >= E) return;
    int s = __ldg(ei + e);
    int d = __ldg(ei + (size_t)E + e);
    int pos = atomicAdd(&g_cur[d], 1);
    g_csr[pos] = s;
}

// ---------------- fused SpMM + MLP1 + MLP2 ----------------
#define KW 16
#define WSP 20
#define ASP 132

struct SmemT {
    __align__(16) unsigned as_f[64][ASP];   // 33.8 KB
    __align__(16) unsigned ws[128][WSP];    // 10.2 KB
};

template <bool RELU, bool TO_SMEM>
__device__ __forceinline__ void gemm_tile(SmemT* sm,
                                          const float* __restrict__ w,
                                          const float* __restrict__ bias,
                                          float* __restrict__ out,
                                          int row0, int n, int tid) {
    int wid = tid >> 5;
    int lane = tid & 31;
    int g = lane >> 2;
    int qt = lane & 3;
    int wm = wid & 3;
    int wn = wid >> 2;

    float acc[8][4];
#pragma unroll
    for (int j = 0; j < 8; ++j)
#pragma unroll
        for (int c = 0; c < 4; ++c) acc[j][c] = 0.0f;

#pragma unroll
    for (int kc = 0; kc < 8; ++kc) {
#pragma unroll
        for (int i = 0; i < 2; ++i) {
            int f4 = tid + 256 * i;
            int col = f4 >> 2;
            int kq = f4 & 3;
            float4 v = __ldg((const float4*)(w + (size_t)col * H + kc * KW) + kq);
            uint4 t;
            t.x = f2tf(v.x); t.y = f2tf(v.y); t.z = f2tf(v.z); t.w = f2tf(v.w);
            *(uint4*)&sm->ws[col][kq * 4] = t;
        }
        __syncthreads();

#pragma unroll
        for (int kk = 0; kk < 2; ++kk) {
            int k0 = kk * 8;
            int ka = kc * KW + k0;
            unsigned a0 = sm->as_f[wm * 16 + g][ka + qt];
            unsigned a1 = sm->as_f[wm * 16 + g + 8][ka + qt];
            unsigned a2 = sm->as_f[wm * 16 + g][ka + qt + 4];
            unsigned a3 = sm->as_f[wm * 16 + g + 8][ka + qt + 4];
#pragma unroll
            for (int j = 0; j < 8; ++j) {
                int nb = wn * 64 + j * 8;
                unsigned b0 = sm->ws[nb + g][k0 + qt];
                unsigned b1 = sm->ws[nb + g][k0 + qt + 4];
                asm volatile(
                    "mma.sync.aligned.m16n8k8.row.col.f32.tf32.tf32.f32 "
                    "{%0,%1,%2,%3}, {%4,%5,%6,%7}, {%8,%9}, {%0,%1,%2,%3};"
                    : "+f"(acc[j][0]), "+f"(acc[j][1]), "+f"(acc[j][2]), "+f"(acc[j][3])
                    : "r"(a0), "r"(a1), "r"(a2), "r"(a3), "r"(b0), "r"(b1));
            }
        }
        __syncthreads();
    }

    int r0l = wm * 16 + g;
    int r1l = r0l + 8;
#pragma unroll
    for (int j = 0; j < 8; ++j) {
        int col0 = wn * 64 + j * 8 + qt * 2;
        float2 bv = __ldg((const float2*)(bias + col0));
        float2 o0, o1;
        o0.x = acc[j][0] + bv.x; o0.y = acc[j][1] + bv.y;
        o1.x = acc[j][2] + bv.x; o1.y = acc[j][3] + bv.y;
        if (RELU) {
            o0.x = fmaxf(o0.x, 0.f); o0.y = fmaxf(o0.y, 0.f);
            o1.x = fmaxf(o1.x, 0.f); o1.y = fmaxf(o1.y, 0.f);
        }
        if (TO_SMEM) {
            uint2 t0, t1;
            t0.x = f2tf(o0.x); t0.y = f2tf(o0.y);
            t1.x = f2tf(o1.x); t1.y = f2tf(o1.y);
            *(uint2*)&sm->as_f[r0l][col0] = t0;
            *(uint2*)&sm->as_f[r1l][col0] = t1;
        } else {
            int gr0 = row0 + r0l, gr1 = row0 + r1l;
            if (gr0 < n) *(float2*)(out + (size_t)gr0 * H + col0) = o0;
            if (gr1 < n) *(float2*)(out + (size_t)gr1 * H + col0) = o1;
        }
    }
}

__device__ __forceinline__ void h8_add(float4& a, float4& b, uint2 u) {
    __half2 h0 = *(__half2*)&u.x;
    __half2 h1 = *(__half2*)&u.y;
    float2 f0 = __half22float2(h0);
    float2 f1 = __half22float2(h1);
    a.x += f0.x; a.y += f0.y; a.z += f1.x; a.w += f1.y;
    (void)b;
}

__global__ __launch_bounds__(256) void k_fused(const float* __restrict__ x,
                                               const float* __restrict__ we,
                                               const float* __restrict__ be,
                                               const float* __restrict__ w1,
                                               const float* __restrict__ b1,
                                               const float* __restrict__ w2,
                                               const float* __restrict__ b2,
                                               float* __restrict__ out, int n) {
    __shared__ SmemT sm;

    int row0 = blockIdx.x * 64;
    int tid = threadIdx.x;
    int wid = tid >> 5;
    int lane = tid & 31;

    float4 w4 = __ldg((const float4*)we + lane);
    float4 b4 = __ldg((const float4*)be + lane);

#pragma unroll 1
    for (int i = 0; i < 8; ++i) {
        int lr = wid * 8 + i;
        int row = row0 + lr;
        float4 acc = make_float4(0.f, 0.f, 0.f, 0.f);
        if (row < n) {
            // fp32 self-term + closed-form edge-attr terms
            float4 xr = __ldg((const float4*)(x + (size_t)row * H) + lane);
            ull ps = __ldg(&g_degsum[row]);
            float dg = (float)(unsigned)(ps >> 48);
            float sw = (float)(ps & 0xFFFFFFFFFFFFull) * (1.0f / 4294967296.0f);

            acc.x = fmaf(sw, w4.x, fmaf(dg, b4.x, xr.x));
            acc.y = fmaf(sw, w4.y, fmaf(dg, b4.y, xr.y));
            acc.z = fmaf(sw, w4.z, fmaf(dg, b4.z, xr.z));
            acc.w = fmaf(sw, w4.w, fmaf(dg, b4.w, xr.w));

            // fp16 neighbor gather: 256B per edge row (lane: 8B = 4 halves)
            int e = __ldg(&g_off[row]);
            int end = __ldg(&g_off[row + 1]);
            for (; e + 4 <= end; e += 4) {
                int s0 = __ldg(g_csr + e);
                int s1 = __ldg(g_csr + e + 1);
                int s2 = __ldg(g_csr + e + 2);
                int s3 = __ldg(g_csr + e + 3);
                uint2 u0 = __ldg((const uint2*)(g_xh + (size_t)s0 * (H / 2)) + lane);
                uint2 u1 = __ldg((const uint2*)(g_xh + (size_t)s1 * (H / 2)) + lane);
                uint2 u2 = __ldg((const uint2*)(g_xh + (size_t)s2 * (H / 2)) + lane);
                uint2 u3 = __ldg((const uint2*)(g_xh + (size_t)s3 * (H / 2)) + lane);
                // pairwise fp16 adds first (exact in fp32 after convert is safer:
                // convert each then fp32 add)
                h8_add(acc, acc, u0);
                h8_add(acc, acc, u1);
                h8_add(acc, acc, u2);
                h8_add(acc, acc, u3);
            }
            for (; e < end; ++e) {
                int s = __ldg(g_csr + e);
                uint2 u = __ldg((const uint2*)(g_xh + (size_t)s * (H / 2)) + lane);
                h8_add(acc, acc, u);
            }
        }
        uint4 t;
        t.x = f2tf(acc.x); t.y = f2tf(acc.y); t.z = f2tf(acc.z); t.w = f2tf(acc.w);
        *(uint4*)&sm.as_f[lr][lane * 4] = t;
    }
    __syncthreads();

    gemm_tile<true, true>(&sm, w1, b1, nullptr, row0, n, tid);
    __syncthreads();

    gemm_tile<false, false>(&sm, w2, b2, out, row0, n, tid);
}

// ---------------- launch ----------------
extern "C" void kernel_launch(void* const* d_in, const int* in_sizes, int n_in,
                              void* d_out, int out_size) {
    const float* x = (const float*)d_in[0];
    const int* ei = (const int*)d_in[1];
    const float* ew = (const float*)d_in[2];
    const float* w_edge = (const float*)d_in[3];
    const float* b_edge = (const float*)d_in[4];
    const float* w1 = (const float*)d_in[5];
    const float* b1 = (const float*)d_in[6];
    const float* w2 = (const float*)d_in[7];
    const float* b2 = (const float*)d_in[8];
    float* out = (float*)d_out;

    int n = in_sizes[0] / H;   // 100000
    int E = in_sizes[1] / 2;   // 1600000

    int eb = (E + 255) / 256;
    int nb = (n + 255) / 256;
    int sb = (n + 1023) / 1024;
    int hb = (n * 32 + 255) / 256;   // n*H/4 float4s

    k_tohalf<<<hb, 256>>>(x, n * 32);
    k_zero<<<nb, 256>>>(n);
    k_hist<<<eb, 256>>>(ei, ew, E);
    k_scan1<<<sb, 1024>>>(n);
    k_scan3<<<sb, 1024>>>(n, E);
    k_fill<<<eb, 256>>>(ei, E);
    k_fused<<<(n + 63) / 64, 256>>>(x, w_edge, b_edge, w1, b1, w2, b2, out, n);
}

// round 7
// speedup vs baseline: 1.1056x; 1.1056x over previous
#include <cuda_runtime.h>

#define H 128
#define NMAX 100000
#define EMAX 1600000

typedef unsigned long long ull;

// ---------------- device scratch (no allocs allowed) ----------------
__device__ ull   g_degsum[NMAX];     // [deg:16][sumw_fixed(2^-32):48]
__device__ int   g_off[NMAX + 1];
__device__ int   g_cur[NMAX];
__device__ int   g_bsum[128];
__device__ int   g_csr[EMAX];

__device__ __forceinline__ unsigned f2tf(float f) {
    unsigned r; asm("cvt.rna.tf32.f32 %0, %1;" : "=r"(r) : "f"(f)); return r;
}

// ---------------- CSR build ----------------
__global__ void k_zero(int n) {
    int i = blockIdx.x * blockDim.x + threadIdx.x;
    if (i < n) g_degsum[i] = 0ull;
}

// 2 edges per thread, vectorized loads.
__global__ void k_hist(const int* __restrict__ ei, const float* __restrict__ ew, int E) {
    int t = blockIdx.x * blockDim.x + threadIdx.x;
    int e = t * 2;
    if (e + 1 < E) {
        int2 d2 = __ldg((const int2*)(ei + (size_t)E + e));
        float2 w2 = __ldg((const float2*)(ew + e));
        atomicAdd(&g_degsum[d2.x], (1ull << 48) + (ull)(w2.x * 4294967296.0f));
        atomicAdd(&g_degsum[d2.y], (1ull << 48) + (ull)(w2.y * 4294967296.0f));
    } else if (e < E) {
        int d = __ldg(ei + (size_t)E + e);
        float w = __ldg(ew + e);
        atomicAdd(&g_degsum[d], (1ull << 48) + (ull)(w * 4294967296.0f));
    }
}

__global__ __launch_bounds__(1024) void k_scan1(int n) {
    __shared__ int sh[1024];
    int tid = threadIdx.x;
    int i = blockIdx.x * 1024 + tid;
    int v = (i < n) ? (int)(g_degsum[i] >> 48) : 0;
    sh[tid] = v;
    __syncthreads();
#pragma unroll
    for (int ofs = 1; ofs < 1024; ofs <<= 1) {
        int t = (tid >= ofs) ? sh[tid - ofs] : 0;
        __syncthreads();
        sh[tid] += t;
        __syncthreads();
    }
    if (i <= n) g_off[i] = sh[tid] - v;
    if (tid == 1023) g_bsum[blockIdx.x] = sh[1023];
}

__global__ __launch_bounds__(1024) void k_scan3(int n, int E) {
    __shared__ int sh[128];
    __shared__ int s_base;
    int tid = threadIdx.x;
    int b = blockIdx.x;
    if (tid < 128) sh[tid] = (tid < b) ? g_bsum[tid] : 0;
    __syncthreads();
    if (tid < 64) sh[tid] += sh[tid + 64];
    __syncthreads();
    if (tid < 32) {
        int v = sh[tid] + sh[tid + 32];
#pragma unroll
        for (int o = 16; o > 0; o >>= 1) v += __shfl_down_sync(0xffffffffu, v, o);
        if (tid == 0) s_base = v;
    }
    __syncthreads();
    int base = s_base;
    int i = b * 1024 + tid;
    if (i < n) {
        int o = g_off[i] + base;
        g_off[i] = o;
        g_cur[i] = o;
    }
    if (i == 0) g_off[n] = E;
}

// 2 edges per thread, vectorized loads.
__global__ void k_fill(const int* __restrict__ ei, int E) {
    int t = blockIdx.x * blockDim.x + threadIdx.x;
    int e = t * 2;
    if (e + 1 < E) {
        int2 s2 = __ldg((const int2*)(ei + e));
        int2 d2 = __ldg((const int2*)(ei + (size_t)E + e));
        g_csr[atomicAdd(&g_cur[d2.x], 1)] = s2.x;
        g_csr[atomicAdd(&g_cur[d2.y], 1)] = s2.y;
    } else if (e < E) {
        int s = __ldg(ei + e);
        int d = __ldg(ei + (size_t)E + e);
        g_csr[atomicAdd(&g_cur[d], 1)] = s;
    }
}

// ---------------- fused SpMM + MLP1 + MLP2 ----------------
#define KW 16
#define WSP 20
#define ASP 132

struct SmemT {
    __align__(16) unsigned as_f[64][ASP];   // 33.8 KB
    __align__(16) unsigned ws[128][WSP];    // 10.2 KB
};

template <bool RELU, bool TO_SMEM>
__device__ __forceinline__ void gemm_tile(SmemT* sm,
                                          const float* __restrict__ w,
                                          const float* __restrict__ bias,
                                          float* __restrict__ out,
                                          int row0, int n, int tid) {
    int wid = tid >> 5;
    int lane = tid & 31;
    int g = lane >> 2;
    int qt = lane & 3;
    int wm = wid & 3;
    int wn = wid >> 2;

    float acc[8][4];
#pragma unroll
    for (int j = 0; j < 8; ++j)
#pragma unroll
        for (int c = 0; c < 4; ++c) acc[j][c] = 0.0f;

#pragma unroll
    for (int kc = 0; kc < 8; ++kc) {
#pragma unroll
        for (int i = 0; i < 2; ++i) {
            int f4 = tid + 256 * i;
            int col = f4 >> 2;
            int kq = f4 & 3;
            float4 v = __ldg((const float4*)(w + (size_t)col * H + kc * KW) + kq);
            uint4 t;
            t.x = f2tf(v.x); t.y = f2tf(v.y); t.z = f2tf(v.z); t.w = f2tf(v.w);
            *(uint4*)&sm->ws[col][kq * 4] = t;
        }
        __syncthreads();

#pragma unroll
        for (int kk = 0; kk < 2; ++kk) {
            int k0 = kk * 8;
            int ka = kc * KW + k0;
            unsigned a0 = sm->as_f[wm * 16 + g][ka + qt];
            unsigned a1 = sm->as_f[wm * 16 + g + 8][ka + qt];
            unsigned a2 = sm->as_f[wm * 16 + g][ka + qt + 4];
            unsigned a3 = sm->as_f[wm * 16 + g + 8][ka + qt + 4];
#pragma unroll
            for (int j = 0; j < 8; ++j) {
                int nb = wn * 64 + j * 8;
                unsigned b0 = sm->ws[nb + g][k0 + qt];
                unsigned b1 = sm->ws[nb + g][k0 + qt + 4];
                asm volatile(
                    "mma.sync.aligned.m16n8k8.row.col.f32.tf32.tf32.f32 "
                    "{%0,%1,%2,%3}, {%4,%5,%6,%7}, {%8,%9}, {%0,%1,%2,%3};"
                    : "+f"(acc[j][0]), "+f"(acc[j][1]), "+f"(acc[j][2]), "+f"(acc[j][3])
                    : "r"(a0), "r"(a1), "r"(a2), "r"(a3), "r"(b0), "r"(b1));
            }
        }
        __syncthreads();
    }

    int r0l = wm * 16 + g;
    int r1l = r0l + 8;
#pragma unroll
    for (int j = 0; j < 8; ++j) {
        int col0 = wn * 64 + j * 8 + qt * 2;
        float2 bv = __ldg((const float2*)(bias + col0));
        float2 o0, o1;
        o0.x = acc[j][0] + bv.x; o0.y = acc[j][1] + bv.y;
        o1.x = acc[j][2] + bv.x; o1.y = acc[j][3] + bv.y;
        if (RELU) {
            o0.x = fmaxf(o0.x, 0.f); o0.y = fmaxf(o0.y, 0.f);
            o1.x = fmaxf(o1.x, 0.f); o1.y = fmaxf(o1.y, 0.f);
        }
        if (TO_SMEM) {
            uint2 t0, t1;
            t0.x = f2tf(o0.x); t0.y = f2tf(o0.y);
            t1.x = f2tf(o1.x); t1.y = f2tf(o1.y);
            *(uint2*)&sm->as_f[r0l][col0] = t0;
            *(uint2*)&sm->as_f[r1l][col0] = t1;
        } else {
            int gr0 = row0 + r0l, gr1 = row0 + r1l;
            if (gr0 < n) *(float2*)(out + (size_t)gr0 * H + col0) = o0;
            if (gr1 < n) *(float2*)(out + (size_t)gr1 * H + col0) = o1;
        }
    }
}

__global__ __launch_bounds__(256) void k_fused(const float* __restrict__ x,
                                               const float* __restrict__ we,
                                               const float* __restrict__ be,
                                               const float* __restrict__ w1,
                                               const float* __restrict__ b1,
                                               const float* __restrict__ w2,
                                               const float* __restrict__ b2,
                                               float* __restrict__ out, int n) {
    __shared__ SmemT sm;

    int row0 = blockIdx.x * 64;
    int tid = threadIdx.x;
    int wid = tid >> 5;
    int lane = tid & 31;

    float4 w4 = __ldg((const float4*)we + lane);
    float4 b4 = __ldg((const float4*)be + lane);

#pragma unroll 1
    for (int i = 0; i < 8; ++i) {
        int lr = wid * 8 + i;
        int row = row0 + lr;
        float4 acc = make_float4(0.f, 0.f, 0.f, 0.f);
        float4 acc2 = make_float4(0.f, 0.f, 0.f, 0.f);
        if (row < n) {
            float4 xr = __ldg((const float4*)(x + (size_t)row * H) + lane);
            ull ps = __ldg(&g_degsum[row]);
            float dg = (float)(unsigned)(ps >> 48);
            float sw = (float)(ps & 0xFFFFFFFFFFFFull) * (1.0f / 4294967296.0f);

            acc.x = fmaf(sw, w4.x, fmaf(dg, b4.x, xr.x));
            acc.y = fmaf(sw, w4.y, fmaf(dg, b4.y, xr.y));
            acc.z = fmaf(sw, w4.z, fmaf(dg, b4.z, xr.z));
            acc.w = fmaf(sw, w4.w, fmaf(dg, b4.w, xr.w));

            int e = __ldg(&g_off[row]);
            int end = __ldg(&g_off[row + 1]);

            // 8-wide unroll, two independent accumulator chains
            for (; e + 8 <= end; e += 8) {
                int s0 = __ldg(g_csr + e);
                int s1 = __ldg(g_csr + e + 1);
                int s2 = __ldg(g_csr + e + 2);
                int s3 = __ldg(g_csr + e + 3);
                int s4 = __ldg(g_csr + e + 4);
                int s5 = __ldg(g_csr + e + 5);
                int s6 = __ldg(g_csr + e + 6);
                int s7 = __ldg(g_csr + e + 7);
                float4 a0 = __ldg((const float4*)(x + (size_t)s0 * H) + lane);
                float4 a1 = __ldg((const float4*)(x + (size_t)s1 * H) + lane);
                float4 a2 = __ldg((const float4*)(x + (size_t)s2 * H) + lane);
                float4 a3 = __ldg((const float4*)(x + (size_t)s3 * H) + lane);
                float4 a4 = __ldg((const float4*)(x + (size_t)s4 * H) + lane);
                float4 a5 = __ldg((const float4*)(x + (size_t)s5 * H) + lane);
                float4 a6 = __ldg((const float4*)(x + (size_t)s6 * H) + lane);
                float4 a7 = __ldg((const float4*)(x + (size_t)s7 * H) + lane);
                acc.x += (a0.x + a1.x) + (a2.x + a3.x);
                acc.y += (a0.y + a1.y) + (a2.y + a3.y);
                acc.z += (a0.z + a1.z) + (a2.z + a3.z);
                acc.w += (a0.w + a1.w) + (a2.w + a3.w);
                acc2.x += (a4.x + a5.x) + (a6.x + a7.x);
                acc2.y += (a4.y + a5.y) + (a6.y + a7.y);
                acc2.z += (a4.z + a5.z) + (a6.z + a7.z);
                acc2.w += (a4.w + a5.w) + (a6.w + a7.w);
            }
            for (; e + 4 <= end; e += 4) {
                int s0 = __ldg(g_csr + e);
                int s1 = __ldg(g_csr + e + 1);
                int s2 = __ldg(g_csr + e + 2);
                int s3 = __ldg(g_csr + e + 3);
                float4 a0 = __ldg((const float4*)(x + (size_t)s0 * H) + lane);
                float4 a1 = __ldg((const float4*)(x + (size_t)s1 * H) + lane);
                float4 a2 = __ldg((const float4*)(x + (size_t)s2 * H) + lane);
                float4 a3 = __ldg((const float4*)(x + (size_t)s3 * H) + lane);
                acc.x += (a0.x + a1.x) + (a2.x + a3.x);
                acc.y += (a0.y + a1.y) + (a2.y + a3.y);
                acc.z += (a0.z + a1.z) + (a2.z + a3.z);
                acc.w += (a0.w + a1.w) + (a2.w + a3.w);
            }
            for (; e < end; ++e) {
                int s = __ldg(g_csr + e);
                float4 a = __ldg((const float4*)(x + (size_t)s * H) + lane);
                acc.x += a.x; acc.y += a.y; acc.z += a.z; acc.w += a.w;
            }
            acc.x += acc2.x; acc.y += acc2.y; acc.z += acc2.z; acc.w += acc2.w;
        }
        uint4 t;
        t.x = f2tf(acc.x); t.y = f2tf(acc.y); t.z = f2tf(acc.z); t.w = f2tf(acc.w);
        *(uint4*)&sm.as_f[lr][lane * 4] = t;
    }
    __syncthreads();

    gemm_tile<true, true>(&sm, w1, b1, nullptr, row0, n, tid);
    __syncthreads();

    gemm_tile<false, false>(&sm, w2, b2, out, row0, n, tid);
}

// ---------------- launch ----------------
// Inputs: 0:x[N,H] 1:edge_index[2,E]i32 2:edge_weight[E] 3:w_edge[H] 4:b_edge[H]
//         5:w1[H,H] 6:b1[H] 7:w2[H,H] 8:b2[H]   out:[N,H]f32
extern "C" void kernel_launch(void* const* d_in, const int* in_sizes, int n_in,
                              void* d_out, int out_size) {
    const float* x = (const float*)d_in[0];
    const int* ei = (const int*)d_in[1];
    const float* ew = (const float*)d_in[2];
    const float* w_edge = (const float*)d_in[3];
    const float* b_edge = (const float*)d_in[4];
    const float* w1 = (const float*)d_in[5];
    const float* b1 = (const float*)d_in[6];
    const float* w2 = (const float*)d_in[7];
    const float* b2 = (const float*)d_in[8];
    float* out = (float*)d_out;

    int n = in_sizes[0] / H;   // 100000
    int E = in_sizes[1] / 2;   // 1600000

    int eb2 = (E / 2 + 255) / 256;   // 2 edges/thread
    int nb = (n + 255) / 256;
    int sb = (n + 1023) / 1024;

    k_zero<<<nb, 256>>>(n);
    k_hist<<<eb2, 256>>>(ei, ew, E);
    k_scan1<<<sb, 1024>>>(n);
    k_scan3<<<sb, 1024>>>(n, E);
    k_fill<<<eb2, 256>>>(ei, E);
    k_fused<<<(n + 63) / 64, 256>>>(x, w_edge, b_edge, w1, b1, w2, b2, out, n);
}